// round 6
// baseline (speedup 1.0000x reference)
#include <cuda_runtime.h>
#include <cuda_bf16.h>
#include <stdint.h>

// Problem constants
#define NN      8192
#define KIN     256
#define OD      64
#define HD      128          // HEADS*OUT_DIM
#define NP      144          // padded GEMM N (multiple of 16 >= 130)
#define NB      130          // real B rows: 128 value cols + 2 denominator cols
#define MT      128          // M rows per CTA
#define KC      64           // K chunk per pipeline stage
#define KSPLIT  2
#define KLEN    (NN/KSPLIT)  // 4096
#define NCHUNK  (KLEN/KC)    // 64
#define NMT     (NN/MT)      // 64

// ---------------- device scratch (no runtime allocation allowed) ----------------
__device__ float          g_h[NN*HD];                 // 4 MB    h = x @ W^T
__device__ float          g_w[NN*2];                  // exp(er) per node/head
__device__ __nv_bfloat16  g_Bhi[NP*NN];               // 2.36 MB B hi, [n][j]; rows 130..143 stay 0
__device__ __nv_bfloat16  g_Blo[NP*NN];               // 2.36 MB B lo
__device__ float          g_part[KSPLIT*NMT*MT*NP];   // 9.4 MB  K-split partials

// ---------------- helpers ----------------
__device__ __forceinline__ uint32_t smem_u32(const void* p) {
    uint32_t a;
    asm("{ .reg .u64 t; cvta.to.shared.u64 t, %1; cvt.u32.u64 %0, t; }" : "=r"(a) : "l"(p));
    return a;
}
#define SWZ(o) ((o) ^ (((o) >> 3) & 0x70))

__device__ __forceinline__ void ldsm_x4(uint32_t& r0, uint32_t& r1, uint32_t& r2, uint32_t& r3,
                                        uint32_t addr) {
    asm volatile("ldmatrix.sync.aligned.m8n8.x4.shared.b16 {%0,%1,%2,%3}, [%4];"
                 : "=r"(r0), "=r"(r1), "=r"(r2), "=r"(r3) : "r"(addr));
}
__device__ __forceinline__ void ldsm_x2(uint32_t& r0, uint32_t& r1, uint32_t addr) {
    asm volatile("ldmatrix.sync.aligned.m8n8.x2.shared.b16 {%0,%1}, [%2];"
                 : "=r"(r0), "=r"(r1) : "r"(addr));
}
// D(fp32) += A(bf16 row) * B(bf16 col) ; m16n8k16
__device__ __forceinline__ void mma_bf16(float* c, uint32_t a0, uint32_t a1, uint32_t a2,
                                         uint32_t a3, uint32_t b0, uint32_t b1) {
    asm volatile("mma.sync.aligned.m16n8k16.row.col.f32.bf16.bf16.f32 "
                 "{%0,%1,%2,%3}, {%4,%5,%6,%7}, {%8,%9}, {%0,%1,%2,%3};"
                 : "+f"(c[0]), "+f"(c[1]), "+f"(c[2]), "+f"(c[3])
                 : "r"(a0), "r"(a1), "r"(a2), "r"(a3), "r"(b0), "r"(b1));
}

// ---------------- K1: h = x @ W^T  (fp32, tiled) ----------------
// grid 128, block 256: per block 64 rows x 128 cols, BK=16
__global__ __launch_bounds__(256) void k1_gemm(const float* __restrict__ x,
                                               const float* __restrict__ W) {
    __shared__ float As[16][64];    // [k][row]
    __shared__ float Bs[16][128];   // [k][col]  (W transposed tile)
    const int t = threadIdx.x;
    const int i0 = blockIdx.x * 64;
    const int tr = t >> 5, tc = t & 31;
    float acc[8][4] = {};

    for (int kt = 0; kt < KIN; kt += 16) {
        {   // x tile 64x16
            int r = t >> 2, kg = (t & 3) * 4;
            float4 v = *(const float4*)(x + (size_t)(i0 + r) * KIN + kt + kg);
            As[kg + 0][r] = v.x; As[kg + 1][r] = v.y; As[kg + 2][r] = v.z; As[kg + 3][r] = v.w;
        }
        {   // W tile transposed: Bs[kk][n] = W[n][kt+kk]
            int n = t >> 1, kg = (t & 1) * 8;
            float4 v0 = *(const float4*)(W + (size_t)n * KIN + kt + kg);
            float4 v1 = *(const float4*)(W + (size_t)n * KIN + kt + kg + 4);
            Bs[kg + 0][n] = v0.x; Bs[kg + 1][n] = v0.y; Bs[kg + 2][n] = v0.z; Bs[kg + 3][n] = v0.w;
            Bs[kg + 4][n] = v1.x; Bs[kg + 5][n] = v1.y; Bs[kg + 6][n] = v1.z; Bs[kg + 7][n] = v1.w;
        }
        __syncthreads();
#pragma unroll
        for (int kk = 0; kk < 16; kk++) {
            float4 a0 = *(float4*)&As[kk][tr * 8];
            float4 a1 = *(float4*)&As[kk][tr * 8 + 4];
            float a[8] = {a0.x, a0.y, a0.z, a0.w, a1.x, a1.y, a1.z, a1.w};
            float b[4];
#pragma unroll
            for (int cc = 0; cc < 4; cc++) b[cc] = Bs[kk][tc + 32 * cc];
#pragma unroll
            for (int rr = 0; rr < 8; rr++)
#pragma unroll
                for (int cc = 0; cc < 4; cc++)
                    acc[rr][cc] = fmaf(a[rr], b[cc], acc[rr][cc]);
        }
        __syncthreads();
    }
#pragma unroll
    for (int rr = 0; rr < 8; rr++)
#pragma unroll
        for (int cc = 0; cc < 4; cc++)
            g_h[(size_t)(i0 + tr * 8 + rr) * HD + tc + 32 * cc] = acc[rr][cc];
}

// ---------------- K1b-a: w[j,h] = exp(er[j,h])  (attn_l cancels in the j-softmax) ----------------
__global__ __launch_bounds__(256) void k1b_er(const float* __restrict__ attn_r) {
    const int j = blockIdx.x * 8 + (threadIdx.x >> 5);
    const int l = threadIdx.x & 31;
    float4 hv = *(const float4*)(g_h + (size_t)j * HD + l * 4);
    const float* h4 = (const float*)&hv;
    const int head = l >> 4;   // lanes 0..15 cover head0 cols, 16..31 head1
    float p = 0.f;
#pragma unroll
    for (int q = 0; q < 4; q++)
        p = fmaf(h4[q], attn_r[head * OD + ((l * 4 + q) & 63)], p);
    float p0 = head ? 0.f : p;
    float p1 = head ? p : 0.f;
#pragma unroll
    for (int off = 16; off; off >>= 1) {
        p0 += __shfl_xor_sync(0xFFFFFFFFu, p0, off);
        p1 += __shfl_xor_sync(0xFFFFFFFFu, p1, off);
    }
    if (l == 0) {
        g_w[j * 2 + 0] = expf(p0);
        g_w[j * 2 + 1] = expf(p1);
    }
}

// ---------------- K1b-b: split-bf16 B: rows 0..127 = w*h, rows 128/129 = w ----------------
__global__ __launch_bounds__(256) void k1b_buildB() {
    const int j = blockIdx.x * 256 + threadIdx.x;
    const int c = blockIdx.y;  // 0..129
    float v;
    if (c < HD)       v = g_w[j * 2 + (c >> 6)] * g_h[(size_t)j * HD + c];
    else              v = g_w[j * 2 + (c - HD)];
    __nv_bfloat16 hi = __float2bfloat16_rn(v);
    float rem = v - __bfloat162float(hi);
    g_Bhi[(size_t)c * NN + j] = hi;
    g_Blo[(size_t)c * NN + j] = __float2bfloat16_rn(rem);
}

// ---------------- K2: adj @ [Bhi|Blo]^T via ldmatrix + mma.sync (base PTX, sm_80+) ----------------
// smem per stage: A 128x64 bf16 (128B rows, SW128)  = 16384
//                 Bhi 144x64 bf16                    = 18432
//                 Blo 144x64 bf16                    = 18432   -> stage 53248, x2 = 106496
#define SA_OFF   0
#define SH_OFF   16384
#define SL_OFF   34816
#define STG      53248
#define SMEM_K2  (2 * STG)

__global__ __launch_bounds__(512, 1)
void k2_agg(const int* __restrict__ adj) {
    extern __shared__ char smem[];
    const uint32_t sb = smem_u32(smem);
    const int t = threadIdx.x, wid = t >> 5, l = t & 31;
    const int mt = blockIdx.x & (NMT - 1), ks = blockIdx.x >> 6;
    const int i0 = mt * MT;
    const int kbase = ks * KLEN;

    // warp tile: 16 (M) x 72 (N); warp grid 8M x 2N
    const int mb = (wid >> 1) * 16;
    const int nb = (wid & 1) * 72;

    float acc[9][4];
#pragma unroll
    for (int nt = 0; nt < 9; nt++)
#pragma unroll
        for (int q = 0; q < 4; q++) acc[nt][q] = 0.f;

    int4 av[4];            // adj prefetch: 16 int32
    int4 bhv[3], blv[3];   // B prefetch (predicated last iter)

    // ---- global load of chunk ch into registers ----
#define LOADG(ch) do {                                                                  \
        const int k0 = kbase + (ch) * KC;                                               \
        _Pragma("unroll")                                                               \
        for (int it = 0; it < 4; it++) {                                                \
            int idx = t + it * 512;                                                     \
            int r = idx >> 4, c4 = idx & 15;                                            \
            av[it] = *(const int4*)(adj + (size_t)(i0 + r) * NN + k0 + c4 * 4);         \
        }                                                                               \
        _Pragma("unroll")                                                               \
        for (int it = 0; it < 3; it++) {                                                \
            int idx = t + it * 512;                                                     \
            if (idx < NP * 8) {                                                         \
                int n = idx >> 3, c = idx & 7;                                          \
                bhv[it] = *((const int4*)(g_Bhi + (size_t)n * NN + k0) + c);            \
                blv[it] = *((const int4*)(g_Blo + (size_t)n * NN + k0) + c);            \
            }                                                                           \
        }                                                                               \
    } while (0)

    // ---- store registers into stage s (convert adj int32 -> bf16 0/1) ----
#define STORES(s) do {                                                                  \
        char* base = smem + (s) * STG;                                                  \
        _Pragma("unroll")                                                               \
        for (int it = 0; it < 4; it++) {                                                \
            int idx = t + it * 512;                                                     \
            int r = idx >> 4, c4 = idx & 15;                                            \
            uint32_t w0 = (av[it].x ? 0x3F80u : 0u) | ((av[it].y ? 0x3F80u : 0u) << 16);\
            uint32_t w1 = (av[it].z ? 0x3F80u : 0u) | ((av[it].w ? 0x3F80u : 0u) << 16);\
            *(uint2*)(base + SA_OFF + SWZ((uint32_t)(r * 128 + c4 * 8))) =              \
                make_uint2(w0, w1);                                                     \
        }                                                                               \
        _Pragma("unroll")                                                               \
        for (int it = 0; it < 3; it++) {                                                \
            int idx = t + it * 512;                                                     \
            if (idx < NP * 8) {                                                         \
                int n = idx >> 3, c = idx & 7;                                          \
                uint32_t sw = SWZ((uint32_t)(n * 128 + c * 16));                        \
                *(int4*)(base + SH_OFF + sw) = bhv[it];                                 \
                *(int4*)(base + SL_OFF + sw) = blv[it];                                 \
            }                                                                           \
        }                                                                               \
    } while (0)

    LOADG(0);
    STORES(0);
    __syncthreads();

    for (int ch = 0; ch < NCHUNK; ch++) {
        const int s = ch & 1;
        if (ch + 1 < NCHUNK) LOADG(ch + 1);

        const uint32_t sA = sb + s * STG + SA_OFF;
        const uint32_t sH = sb + s * STG + SH_OFF;
        const uint32_t sL = sb + s * STG + SL_OFF;
        const int lm = l & 15;

#pragma unroll
        for (int q = 0; q < 4; q++) {
            uint32_t a0, a1, a2, a3;
            {
                uint32_t off = (uint32_t)((mb + lm) * 128 + q * 32 + (l >> 4) * 16);
                ldsm_x4(a0, a1, a2, a3, sA + SWZ(off));
            }
            // 4 x (ldmatrix.x4 over 2 n-tiles) + 1 x (ldmatrix.x2), for hi then lo
            const int brow = (l & 7) + ((l >> 4) << 3);   // x4 lane->row within 16-row group
            const int bhalf = (l >> 3) & 1;
#pragma unroll
            for (int p = 0; p < 4; p++) {
                uint32_t off = (uint32_t)((nb + p * 16 + brow) * 128 + q * 32 + bhalf * 16);
                uint32_t sw = SWZ(off);
                uint32_t b0, b1, b2, b3;
                ldsm_x4(b0, b1, b2, b3, sH + sw);
                mma_bf16(acc[p * 2 + 0], a0, a1, a2, a3, b0, b1);
                mma_bf16(acc[p * 2 + 1], a0, a1, a2, a3, b2, b3);
                ldsm_x4(b0, b1, b2, b3, sL + sw);
                mma_bf16(acc[p * 2 + 0], a0, a1, a2, a3, b0, b1);
                mma_bf16(acc[p * 2 + 1], a0, a1, a2, a3, b2, b3);
            }
            {
                uint32_t off = (uint32_t)((nb + 64 + (lm & 7)) * 128 + q * 32 + (lm >> 3) * 16);
                uint32_t sw = SWZ(off);
                uint32_t b0, b1;
                ldsm_x2(b0, b1, sH + sw);
                mma_bf16(acc[8], a0, a1, a2, a3, b0, b1);
                ldsm_x2(b0, b1, sL + sw);
                mma_bf16(acc[8], a0, a1, a2, a3, b0, b1);
            }
        }

        if (ch + 1 < NCHUNK) STORES((ch + 1) & 1);
        __syncthreads();
    }

    // epilogue: write fp32 partials. mma C frag: c0,c1 -> (row, col..col+1), c2,c3 -> (row+8)
    {
        const int row0 = mb + (l >> 2);
        float* dst = g_part + (size_t)blockIdx.x * MT * NP;
#pragma unroll
        for (int nt = 0; nt < 9; nt++) {
            const int col = nb + nt * 8 + (l & 3) * 2;
            *(float2*)(dst + (size_t)row0 * NP + col)       = make_float2(acc[nt][0], acc[nt][1]);
            *(float2*)(dst + (size_t)(row0 + 8) * NP + col) = make_float2(acc[nt][2], acc[nt][3]);
        }
    }
#undef LOADG
#undef STORES
}

// ---------------- K3: combine K-split partials, divide by denominator ----------------
__global__ __launch_bounds__(128) void k3_finish(float* __restrict__ out) {
    const int i = blockIdx.x;           // node row
    const int n = threadIdx.x;          // output col 0..127
    const int mt = i >> 7, row = i & 127;
    float num = 0.f, den = 0.f;
#pragma unroll
    for (int ks = 0; ks < KSPLIT; ks++) {
        const float* p = g_part + ((size_t)(ks * NMT + mt) * MT + row) * NP;
        num += p[n];
        den += p[HD + (n >> 6)];
    }
    out[(size_t)i * HD + n] = num / den;
}

// ---------------- launch ----------------
extern "C" void kernel_launch(void* const* d_in, const int* in_sizes, int n_in,
                              void* d_out, int out_size) {
    (void)in_sizes; (void)n_in; (void)out_size;
    const float* x      = (const float*)d_in[0];
    const int*   adj    = (const int*)d_in[1];
    const float* W      = (const float*)d_in[2];
    // d_in[3] = attn_l: constant along the softmax axis -> cancels, unused
    const float* attn_r = (const float*)d_in[4];
    float* out = (float*)d_out;

    // idempotent, not a stream op — safe under graph capture
    cudaFuncSetAttribute(k2_agg, cudaFuncAttributeMaxDynamicSharedMemorySize, SMEM_K2);

    k1_gemm<<<NN / 64, 256>>>(x, W);
    k1b_er<<<NN / 8, 256>>>(attn_r);
    {
        dim3 g(NN / 256, NB);
        k1b_buildB<<<g, 256>>>();
    }
    k2_agg<<<KSPLIT * NMT, 512, SMEM_K2>>>(adj);
    k3_finish<<<NN, 128>>>(out);
}